// round 14
// baseline (speedup 1.0000x reference)
#include <cuda_runtime.h>
#include <cstdint>
#include <math.h>

#define BB 64
#define TMAX 256
#define PP 64
#define DD 128
#define CC 10
#define TBASE 367

// Scratch (no cudaMalloc allowed)
__device__ int   d_len[BB];
__device__ int   d_off[BB + 1];
__device__ float d_E[TBASE * CC];   // E[date*C + c]
__device__ int   d_done;            // producer counter (monotone across replays;
                                    //  producer outputs are replay-invariant)

// Grid layout: producers first (wave-1 guaranteed), then consumers.
#define BID_LEN  0                  // bid 0: lengths + prefix sum
#define NB_E     74                 // bids 1..74: E (5 dates per block)
#define NB_PROD  (1 + NB_E)         // 75
#define TCHUNK   32
#define NB_CONS  (BB * (TMAX / TCHUNK))   // 512
#define NB_GRID  (NB_PROD + NB_CONS)      // 587  (<= 4 blocks/SM * 148 = 592)

// -log2(TBASE)/64 for inv_freq = TBASE^(-2k/D) = 2^(k * NEG_L2B_64)
#define NEG_L2B_64 (-0.1331193181f)

// ---------------------------------------------------------------------------
// Single fused kernel, single wave.
// ---------------------------------------------------------------------------
__global__ void __launch_bounds__(320, 5) k_all(const float* __restrict__ x,
                                                const int*   __restrict__ dates,
                                                const float* __restrict__ W,
                                                const float* __restrict__ bias,
                                                float* __restrict__ out) {
    int bid = blockIdx.x;
    int tid = threadIdx.x;

    if (bid < NB_PROD) {
        // =================== PRODUCERS ===================
        if (bid == BID_LEN) {
            // ---- lengths + exclusive prefix sum (first 256 threads)
            __shared__ int s_len[BB];
            if (tid < 256) {
                int b = tid >> 2;        // 4 threads per row
                int k = tid & 3;
                const int4* row4 = (const int4*)(dates + b * TMAX);
                int last = -1;
                #pragma unroll
                for (int i = 0; i < 16; ++i) {
                    int idx = k + i * 4;
                    int4 v = row4[idx];
                    int bt = idx * 4;
                    if (v.x != 0) last = bt;
                    if (v.y != 0) last = bt + 1;
                    if (v.z != 0) last = bt + 2;
                    if (v.w != 0) last = bt + 3;
                }
                last = max(last, __shfl_down_sync(0xffffffffu, last, 2, 4));
                last = max(last, __shfl_down_sync(0xffffffffu, last, 1, 4));
                if (k == 0) {
                    int L = (last < 0) ? (TMAX - 1) : last;
                    s_len[b] = L;
                    d_len[b] = L;
                }
            }
            __syncthreads();
            if (tid == 0) {
                int acc = 0;
                #pragma unroll
                for (int i = 0; i < BB; ++i) { d_off[i] = acc; acc += s_len[i]; }
                d_off[BB] = acc;
            }
        } else {
            // ---- E[pos,c] = sinusoid_table[pos,:] . W[c,:]
            // 5 dates per block, 64 threads per date; fp32 fast path.
            __shared__ float s_part[5][CC][2];
            int sub = tid >> 6;          // 0..4: date within block
            int k   = tid & 63;          // 0..63: frequency index
            int pos = (bid - 1) * 5 + sub;

            float s = 0.0f, co = 0.0f;
            if (pos < TBASE) {
                float inv_freq = exp2f((float)k * NEG_L2B_64);
                sincosf((float)pos * inv_freq, &s, &co);
            }
            #pragma unroll
            for (int c = 0; c < CC; ++c) {
                float v = fmaf(s, W[c * DD + 2 * k], co * W[c * DD + 2 * k + 1]);
                #pragma unroll
                for (int o = 16; o > 0; o >>= 1)
                    v += __shfl_down_sync(0xffffffffu, v, o);
                if ((tid & 31) == 0)
                    s_part[sub][c][(tid >> 5) & 1] = v;
            }
            __syncthreads();
            if (k < CC && pos < TBASE)
                d_E[pos * CC + k] = s_part[sub][k][0] + s_part[sub][k][1];
        }
        __syncthreads();
        if (tid == 0) {
            __threadfence();
            atomicAdd(&d_done, 1);
        }
        return;
    }

    // =================== CONSUMERS ===================
    __shared__ float s_y[CC * PP];       // Y[b][c][p], 2.5 KB
    __shared__ int   s_dates[TCHUNK];

    int cid = bid - NB_PROD;
    int b   = cid >> 3;                  // 8 chunks per batch row
    int t0  = (cid & 7) * TCHUNK;

    int w    = tid >> 5;                 // 0..9
    int lane = tid & 31;

    // ---- Phase 1: compute own Y[b,:,:] (independent of producers)
    {
        const float4* x4 = (const float4*)x;
        const float4* W4 = (const float4*)W;
        for (int p = w; p < PP; p += 10) {
            float4 xv = x4[(size_t)(b * PP + p) * (DD / 4) + lane];
            #pragma unroll
            for (int c = 0; c < CC; ++c) {
                float4 wv = W4[c * (DD / 4) + lane];
                float v = fmaf(xv.x, wv.x,
                          fmaf(xv.y, wv.y,
                          fmaf(xv.z, wv.z, xv.w * wv.w)));
                #pragma unroll
                for (int o = 16; o > 0; o >>= 1)
                    v += __shfl_down_sync(0xffffffffu, v, o);
                if (lane == 0)
                    s_y[c * PP + p] = v + bias[c];
            }
        }
    }

    // ---- prefetch dates (input, independent of producers)
    if (tid < TCHUNK) s_dates[tid] = __ldg(&dates[b * TMAX + t0 + tid]);
    __syncthreads();

    // ---- wait for producers (E table, lengths/offsets)
    if (tid == 0) {
        while (*((volatile int*)&d_done) < NB_PROD)
            __nanosleep(64);
        __threadfence();
    }
    __syncthreads();

    int L = d_len[b];
    if (t0 >= L) return;                 // uniform per block

    int slot = tid >= 160 ? 1 : 0;       // token parity slot (warps 0-4 / 5-9)
    int r    = tid - slot * 160;         // 0..159
    int c    = r >> 4;                   // 0..9
    int p4   = r & 15;                   // 0..15

    int n0   = d_off[b];
    int Ntot = d_off[BB];

    float4 y = ((const float4*)s_y)[c * (PP / 4) + p4];
    float4* out4 = (float4*)out;
    size_t mask_base = (size_t)Ntot * (CC * PP);

    #pragma unroll 4
    for (int i = 0; i < TCHUNK / 2; ++i) {
        int t = t0 + 2 * i + slot;
        if (t >= L) continue;
        int date = s_dates[2 * i + slot];
        float e = __ldg(&d_E[date * CC + c]);
        int n = n0 + t;
        out4[(size_t)n * 160 + r] =
            make_float4(y.x + e, y.y + e, y.z + e, y.w + e);
        if (r < 2)
            out[mask_base + (size_t)n * 2 + r] = (r == 0) ? (float)b : (float)t;
    }
}

// ---------------------------------------------------------------------------
extern "C" void kernel_launch(void* const* d_in, const int* in_sizes, int n_in,
                              void* d_out, int out_size) {
    const float* x     = (const float*)d_in[0];
    // d_in[1] = attentions (unused by the reference computation)
    const int*   dates = (const int*)d_in[2];
    const float* W     = (const float*)d_in[3];
    const float* bias  = (const float*)d_in[4];
    float* out = (float*)d_out;

    k_all<<<NB_GRID, 320>>>(x, dates, W, bias, out);
}

// round 16
// speedup vs baseline: 1.7977x; 1.7977x over previous
#include <cuda_runtime.h>
#include <cstdint>
#include <math.h>

#define BB 64
#define TMAX 256
#define PP 64
#define DD 128
#define CC 10
#define TBASE 367

// Scratch (no cudaMalloc allowed)
__device__ int    d_len[BB];
__device__ int    d_off[BB + 1];
__device__ float  d_E[TBASE * CC];            // E[date*C + c]
__device__ float4 d_Y4[BB * CC * (PP / 4)];   // Y[b][c][p] as float4 along p

// k_setup role partition
#define NB_Y    512                 // blocks 0..511: Y (8 warps, one (b,p) per warp)
#define NB_E    92                  // blocks 512..603: E (4 dates per block)
#define BID_LEN (NB_Y + NB_E)       // block 604: lengths + prefix sum
#define NB_SETUP (BID_LEN + 1)

// -log2(TBASE)/64 for inv_freq = TBASE^(-2k/D) = 2^(k * NEG_L2B_64)
#define NEG_L2B_64 (-0.1331193181f)

// ---------------------------------------------------------------------------
// Fused setup kernel: Y precompute + E table + ragged lengths/offsets.
// Each block triggers programmatic launch completion once its stores are done.
// ---------------------------------------------------------------------------
__global__ void __launch_bounds__(256) k_setup(const float* __restrict__ x,
                                               const int*   __restrict__ dates,
                                               const float* __restrict__ W,
                                               const float* __restrict__ bias) {
    int bid = blockIdx.x;
    int tid = threadIdx.x;

    if (bid < NB_Y) {
        // ---- Y[b][c][p] = bias[c] + x[b,p,:] . W[c,:]  (one warp per (b,p))
        int w    = bid * 8 + (tid >> 5);
        int lane = tid & 31;
        int b = w / PP;
        int p = w % PP;

        const float4* x4 = (const float4*)x;
        float4 xv = x4[(size_t)(b * PP + p) * (DD / 4) + lane];
        const float4* W4 = (const float4*)W;
        float* Yf = (float*)d_Y4;

        #pragma unroll
        for (int c = 0; c < CC; ++c) {
            float4 wv = W4[c * (DD / 4) + lane];
            float v = fmaf(xv.x, wv.x, fmaf(xv.y, wv.y, fmaf(xv.z, wv.z, xv.w * wv.w)));
            #pragma unroll
            for (int o = 16; o > 0; o >>= 1)
                v += __shfl_down_sync(0xffffffffu, v, o);
            if (lane == 0)
                Yf[(b * CC + c) * PP + p] = v + bias[c];
        }
    } else if (bid < BID_LEN) {
        // ---- E[pos,c] = sinusoid_table[pos,:] . W[c,:]
        // 4 dates per block; 64 threads per date; fp32 fast path
        // (inv_freq via exp2f, accurate sincosf; rel err ~2e-6 vs 1e-3 gate).
        __shared__ float s_part[4][CC][2];

        int sub = tid >> 6;           // 0..3: date within block
        int k   = tid & 63;           // 0..63: frequency index (j = 2k, 2k+1)
        int pos = (bid - NB_Y) * 4 + sub;

        float s = 0.0f, co = 0.0f;
        if (pos < TBASE) {
            float inv_freq = exp2f((float)k * NEG_L2B_64);
            sincosf((float)pos * inv_freq, &s, &co);
        }

        #pragma unroll
        for (int c = 0; c < CC; ++c) {
            float v = fmaf(s, W[c * DD + 2 * k], co * W[c * DD + 2 * k + 1]);
            #pragma unroll
            for (int o = 16; o > 0; o >>= 1)
                v += __shfl_down_sync(0xffffffffu, v, o);
            if ((tid & 31) == 0)
                s_part[sub][c][(tid >> 5) & 1] = v;
        }
        __syncthreads();
        if (k < CC && pos < TBASE)
            d_E[pos * CC + k] = s_part[sub][k][0] + s_part[sub][k][1];
    } else {
        // ---- lengths: last-nonzero index per row, then exclusive prefix sum
        __shared__ int s_len[BB];
        int b = tid >> 2;            // 4 threads per row
        int k = tid & 3;
        const int4* row4 = (const int4*)(dates + b * TMAX);
        int last = -1;
        #pragma unroll
        for (int i = 0; i < 16; ++i) {
            int idx = k + i * 4;     // int4 index (i ascending => keep max)
            int4 v = row4[idx];
            int bt = idx * 4;
            if (v.x != 0) last = bt;
            if (v.y != 0) last = bt + 1;
            if (v.z != 0) last = bt + 2;
            if (v.w != 0) last = bt + 3;
        }
        last = max(last, __shfl_down_sync(0xffffffffu, last, 2, 4));
        last = max(last, __shfl_down_sync(0xffffffffu, last, 1, 4));
        if (k == 0) {
            int L = (last < 0) ? (TMAX - 1) : last;
            s_len[b] = L;
            d_len[b] = L;
        }
        __syncthreads();
        if (tid == 0) {
            int acc = 0;
            #pragma unroll
            for (int i = 0; i < BB; ++i) { d_off[i] = acc; acc += s_len[i]; }
            d_off[BB] = acc;
        }
    }

    // Signal PDL: this block's setup stores are issued.
    cudaTriggerProgrammaticLaunchCompletion();
}

// ---------------------------------------------------------------------------
// Write kernel (R4 shape — at the chip store ceiling). Launched with PDL:
// independent prologue runs concurrently with k_setup; dependent reads come
// after cudaGridDependencySynchronize().
// ---------------------------------------------------------------------------
#define TCHUNK 32

__global__ void __launch_bounds__(320) k_write(const int* __restrict__ dates,
                                               float* __restrict__ out) {
    __shared__ int s_dates[TCHUNK];
    int b  = blockIdx.y;
    int t0 = blockIdx.x * TCHUNK;

    int tid  = threadIdx.x;              // 0..319
    int slot = tid >= 160 ? 1 : 0;       // token parity slot (warps 0-4 / 5-9)
    int r    = tid - slot * 160;         // 0..159
    int c    = r >> 4;                   // 0..9
    int p4   = r & 15;                   // 0..15

    // Independent prologue: prefetch dates (input tensor, not setup output).
    if (tid < TCHUNK) s_dates[tid] = __ldg(&dates[b * TMAX + t0 + tid]);

    // Wait for k_setup's grid (full memory visibility guaranteed).
    cudaGridDependencySynchronize();
    __syncthreads();

    int L = d_len[b];
    if (t0 >= L) return;                 // uniform per block

    int n0   = d_off[b];
    int Ntot = d_off[BB];

    float4 y = d_Y4[(b * CC + c) * (PP / 4) + p4];
    float4* out4 = (float4*)out;
    size_t mask_base = (size_t)Ntot * (CC * PP);

    #pragma unroll 4
    for (int i = 0; i < TCHUNK / 2; ++i) {
        int t = t0 + 2 * i + slot;
        if (t >= L) continue;
        int date = s_dates[2 * i + slot];
        float e = __ldg(&d_E[date * CC + c]);
        int n = n0 + t;
        out4[(size_t)n * 160 + r] =
            make_float4(y.x + e, y.y + e, y.z + e, y.w + e);
        if (r < 2)
            out[mask_base + (size_t)n * 2 + r] = (r == 0) ? (float)b : (float)t;
    }
}

// ---------------------------------------------------------------------------
extern "C" void kernel_launch(void* const* d_in, const int* in_sizes, int n_in,
                              void* d_out, int out_size) {
    const float* x     = (const float*)d_in[0];
    // d_in[1] = attentions (unused by the reference computation)
    const int*   dates = (const int*)d_in[2];
    const float* W     = (const float*)d_in[3];
    const float* bias  = (const float*)d_in[4];
    float* out = (float*)d_out;

    k_setup<<<NB_SETUP, 256>>>(x, dates, W, bias);

    // k_write with programmatic dependent launch: overlaps its launch +
    // prologue with k_setup's execution.
    cudaLaunchConfig_t cfg = {};
    cfg.gridDim  = dim3(TMAX / TCHUNK, BB, 1);
    cfg.blockDim = dim3(320, 1, 1);
    cfg.dynamicSmemBytes = 0;
    cfg.stream = 0;
    cudaLaunchAttribute attrs[1];
    attrs[0].id = cudaLaunchAttributeProgrammaticStreamSerialization;
    attrs[0].val.programmaticStreamSerializationAllowed = 1;
    cfg.attrs = attrs;
    cfg.numAttrs = 1;
    cudaLaunchKernelEx(&cfg, k_write, dates, out);
}